// round 5
// baseline (speedup 1.0000x reference)
#include <cuda_runtime.h>
#include <math.h>

#define Bn   65536
#define Tn   5
#define OBSn 128
#define ACTn 32
#define Hn   64
#define BT   (Bn*Tn)
#define EPSf 1e-12f

typedef unsigned long long u64;

// ---------------- scratch (device globals; no allocation allowed) ----------------
__device__ float g_x[BT * Hn];          // MLP output, [B*T, 64]
__device__ float g_ys[2][BT * Hn];      // LSTM outputs per direction (bw in reversed-time order)

extern __shared__ float smem[];

// ---------------- packed f32x2 helpers (FFMA2 — ptxas never emits this itself) ----
__device__ __forceinline__ u64 splat2(float x) {
    u64 r; asm("mov.b64 %0, {%1, %1};" : "=l"(r) : "f"(x)); return r;
}
__device__ __forceinline__ void ffma2(u64& d, u64 a, u64 b) {
    asm("fma.rn.f32x2 %0, %1, %2, %0;" : "+l"(d) : "l"(a), "l"(b));
}
__device__ __forceinline__ void lds_v2u64(u64& a, u64& b, unsigned addr) {
    asm volatile("ld.shared.v2.u64 {%0, %1}, [%2];" : "=l"(a), "=l"(b) : "r"(addr));
}
__device__ __forceinline__ float2 unpack2(u64 v) {
    float2 f; asm("mov.b64 {%0, %1}, %2;" : "=f"(f.x), "=f"(f.y) : "l"(v)); return f;
}

// fast, accurate-enough (~1e-6) gate nonlinearities
__device__ __forceinline__ float sig_f(float x) {
    return __fdividef(1.f, 1.f + __expf(-x));
}
__device__ __forceinline__ float tanh_f(float x) {
    return __fdividef(2.f, 1.f + __expf(-2.f * x)) - 1.f;
}

#define CP16(dst, src) asm volatile("cp.async.ca.shared.global [%0], [%1], 16;" :: "r"(dst), "l"(src))
#define CP_COMMIT()    asm volatile("cp.async.commit_group;")

// =====================================================================================
// Kernel 1: fused MLP.  Block = 128 rows of [B*T], 256 threads.
// Thread GEMM tile = 8 rows x 4 cols (acc in packed f32x2). A loaded as float4 per 4 k.
// =====================================================================================
__global__ __launch_bounds__(256)
void mlp_kernel(const float* __restrict__ ud, const float* __restrict__ act,
                const float* __restrict__ ln0g, const float* __restrict__ ln0b,
                const float* __restrict__ W1, const float* __restrict__ b1,
                const float* __restrict__ ln1g, const float* __restrict__ ln1b,
                const float* __restrict__ W2, const float* __restrict__ b2,
                const float* __restrict__ ln2g, const float* __restrict__ ln2b)
{
    float* sW  = smem;                 // 8192 floats (W1, then W2)
    float* sX  = sW + 128 * 64;        // 128 * 132 = 16896
    float* sX2 = sX + 128 * 132;       // 128 * 100 = 12800
    float* sP  = sX2 + 128 * 100;      // 640

    const unsigned sW_a = (unsigned)__cvta_generic_to_shared(sW);

    const int tid = threadIdx.x;
    // W1: 2048 float4
    #pragma unroll
    for (int j = 0; j < 8; j++) {
        int f = tid + j * 256;
        reinterpret_cast<float4*>(sW)[f] = reinterpret_cast<const float4*>(W1)[f];
    }
    if (tid < 128) { sP[tid] = ln0g[tid]; sP[128 + tid] = ln0b[tid]; }
    if (tid < 64) {
        sP[256 + tid] = b1[tid];  sP[320 + tid] = ln1g[tid]; sP[384 + tid] = ln1b[tid];
        sP[448 + tid] = b2[tid];  sP[512 + tid] = ln2g[tid]; sP[576 + tid] = ln2b[tid];
    }

    const int r0 = blockIdx.x * 128;

    // ud tile 128 x 128 -> sX (stride 132)
    #pragma unroll
    for (int j = 0; j < 16; j++) {
        int f = tid + j * 256;              // 4096 float4
        int row = f >> 5, c4 = f & 31;
        float4 v = reinterpret_cast<const float4*>(ud + (size_t)(r0 + row) * 128)[c4];
        *reinterpret_cast<float4*>(&sX[row * 132 + c4 * 4]) = v;
    }
    // action tile 128 x 32 -> sX2 cols [64,96)
    #pragma unroll
    for (int j = 0; j < 4; j++) {
        int f = tid + j * 256;              // 1024 float4
        int row = f >> 3, c4 = f & 7;
        float4 v = reinterpret_cast<const float4*>(act + (size_t)(r0 + row) * 32)[c4];
        *reinterpret_cast<float4*>(&sX2[row * 100 + 64 + c4 * 4]) = v;
    }
    __syncthreads();

    const int w = tid >> 5, lane = tid & 31;

    // LN0 over 128 features: warp per row, 16 rows/warp
    for (int rr = 0; rr < 16; rr++) {
        int row = w * 16 + rr;
        float v0 = sX[row * 132 + lane];
        float v1 = sX[row * 132 + lane + 32];
        float v2 = sX[row * 132 + lane + 64];
        float v3 = sX[row * 132 + lane + 96];
        float s = v0 + v1 + v2 + v3;
        float q = v0 * v0 + v1 * v1 + v2 * v2 + v3 * v3;
        #pragma unroll
        for (int o = 16; o; o >>= 1) { s += __shfl_xor_sync(~0u, s, o); q += __shfl_xor_sync(~0u, q, o); }
        float m = s * (1.f / 128.f);
        float var = q * (1.f / 128.f) - m * m;
        float rs = rsqrtf(var + EPSf);
        sX[row * 132 + lane]      = (v0 - m) * rs * sP[lane]      + sP[128 + lane];
        sX[row * 132 + lane + 32] = (v1 - m) * rs * sP[lane + 32] + sP[128 + lane + 32];
        sX[row * 132 + lane + 64] = (v2 - m) * rs * sP[lane + 64] + sP[128 + lane + 64];
        sX[row * 132 + lane + 96] = (v3 - m) * rs * sP[lane + 96] + sP[128 + lane + 96];
    }
    __syncthreads();

    const int rg = tid >> 4, cg = tid & 15;
    const int ry = rg * 8, cx = cg * 4;

    // GEMM1: (128x128)@(128x64), thread tile 8 rows x 4 cols
    u64 acc[8][2];
    #pragma unroll
    for (int i = 0; i < 8; i++) { acc[i][0] = 0ull; acc[i][1] = 0ull; }

    for (int k = 0; k < 128; k += 4) {
        float4 a4[8];
        #pragma unroll
        for (int i = 0; i < 8; i++)
            a4[i] = *reinterpret_cast<const float4*>(&sX[(ry + i) * 132 + k]);
        u64 w0[4], w1[4];
        #pragma unroll
        for (int kk = 0; kk < 4; kk++)
            lds_v2u64(w0[kk], w1[kk], sW_a + (unsigned)((k + kk) * 64 + cx) * 4u);
        #pragma unroll
        for (int kk = 0; kk < 4; kk++) {
            #pragma unroll
            for (int i = 0; i < 8; i++) {
                const float* ap = &a4[i].x;
                u64 s = splat2(ap[kk]);
                ffma2(acc[i][0], s, w0[kk]);
                ffma2(acc[i][1], s, w1[kk]);
            }
        }
    }
    __syncthreads();   // all sX + sW(W1) reads done

    // load W2 (96x64 = 1536 float4) into the W buffer
    #pragma unroll
    for (int j = 0; j < 6; j++) {
        int f = tid + j * 256;
        reinterpret_cast<float4*>(sW)[f] = reinterpret_cast<const float4*>(W2)[f];
    }

    // y1 = acc + b1 -> sX
    #pragma unroll
    for (int i = 0; i < 8; i++) {
        float2 p0 = unpack2(acc[i][0]);
        float2 p1 = unpack2(acc[i][1]);
        float4 o;
        o.x = p0.x + sP[256 + cx + 0];
        o.y = p0.y + sP[256 + cx + 1];
        o.z = p1.x + sP[256 + cx + 2];
        o.w = p1.y + sP[256 + cx + 3];
        *reinterpret_cast<float4*>(&sX[(ry + i) * 132 + cx]) = o;
    }
    __syncthreads();

    // LN1 + relu -> sX2 cols [0,64)
    for (int rr = 0; rr < 16; rr++) {
        int row = w * 16 + rr;
        float v0 = sX[row * 132 + lane];
        float v1 = sX[row * 132 + lane + 32];
        float s = v0 + v1, q = v0 * v0 + v1 * v1;
        #pragma unroll
        for (int o = 16; o; o >>= 1) { s += __shfl_xor_sync(~0u, s, o); q += __shfl_xor_sync(~0u, q, o); }
        float m = s * (1.f / 64.f);
        float var = q * (1.f / 64.f) - m * m;
        float rs = rsqrtf(var + EPSf);
        float y0 = (v0 - m) * rs * sP[320 + lane]      + sP[384 + lane];
        float y1 = (v1 - m) * rs * sP[320 + lane + 32] + sP[384 + lane + 32];
        sX2[row * 100 + lane]      = fmaxf(y0, 0.f);
        sX2[row * 100 + lane + 32] = fmaxf(y1, 0.f);
    }
    __syncthreads();   // W2 + sX2 ready

    // GEMM2: (128x96)@(96x64)
    u64 acc2[8][2];
    #pragma unroll
    for (int i = 0; i < 8; i++) { acc2[i][0] = 0ull; acc2[i][1] = 0ull; }

    for (int k = 0; k < 96; k += 4) {
        float4 a4[8];
        #pragma unroll
        for (int i = 0; i < 8; i++)
            a4[i] = *reinterpret_cast<const float4*>(&sX2[(ry + i) * 100 + k]);
        u64 w0[4], w1[4];
        #pragma unroll
        for (int kk = 0; kk < 4; kk++)
            lds_v2u64(w0[kk], w1[kk], sW_a + (unsigned)((k + kk) * 64 + cx) * 4u);
        #pragma unroll
        for (int kk = 0; kk < 4; kk++) {
            #pragma unroll
            for (int i = 0; i < 8; i++) {
                const float* ap = &a4[i].x;
                u64 s = splat2(ap[kk]);
                ffma2(acc2[i][0], s, w0[kk]);
                ffma2(acc2[i][1], s, w1[kk]);
            }
        }
    }
    __syncthreads();

    // y2 = acc2 + b2 -> sX
    #pragma unroll
    for (int i = 0; i < 8; i++) {
        float2 p0 = unpack2(acc2[i][0]);
        float2 p1 = unpack2(acc2[i][1]);
        float4 o;
        o.x = p0.x + sP[448 + cx + 0];
        o.y = p0.y + sP[448 + cx + 1];
        o.z = p1.x + sP[448 + cx + 2];
        o.w = p1.y + sP[448 + cx + 3];
        *reinterpret_cast<float4*>(&sX[(ry + i) * 132 + cx]) = o;
    }
    __syncthreads();

    // LN2 + relu -> global g_x
    for (int rr = 0; rr < 16; rr++) {
        int row = w * 16 + rr;
        float v0 = sX[row * 132 + lane];
        float v1 = sX[row * 132 + lane + 32];
        float s = v0 + v1, q = v0 * v0 + v1 * v1;
        #pragma unroll
        for (int o = 16; o; o >>= 1) { s += __shfl_xor_sync(~0u, s, o); q += __shfl_xor_sync(~0u, q, o); }
        float m = s * (1.f / 64.f);
        float var = q * (1.f / 64.f) - m * m;
        float rs = rsqrtf(var + EPSf);
        float y0 = (v0 - m) * rs * sP[512 + lane]      + sP[576 + lane];
        float y1 = (v1 - m) * rs * sP[512 + lane + 32] + sP[576 + lane + 32];
        size_t base = (size_t)(r0 + row) * 64;
        g_x[base + lane]      = fmaxf(y0, 0.f);
        g_x[base + lane + 32] = fmaxf(y1, 0.f);
    }
}

// =====================================================================================
// Kernel 2: persistent bidirectional LSTM.
//   grid = (512, 2): 128 batch rows per CTA, blockIdx.y = direction. 512 threads.
//   Thread tile = 8 rows x (4 gates x 2 hcols). c in regs; h via smem; K resident.
// Weight layout (plane-permuted, conflict-free LDS.128):
//   sKp[k*256 + plane*128 + tx*4 + {0..3}] = { g_lo[2tx], g_lo[2tx+1], g_hi[2tx], g_hi[2tx+1] }
//   plane 0 -> gates (i, j); plane 1 -> gates (f, o)
// =====================================================================================
__global__ __launch_bounds__(512, 1)
void lstm_persistent_kernel(const float* __restrict__ fw_k, const float* __restrict__ fw_b,
                            const float* __restrict__ bw_k, const float* __restrict__ bw_b,
                            const int* __restrict__ au)
{
    float* sKp  = smem;                  // 32768
    float* xbuf = smem + 32768;          // 2 x 128 x 64
    float* sH   = smem + 49152;          // 128 x 66
    int*   sAu  = (int*)(smem + 57600);  // 128

    const unsigned sKp_a = (unsigned)__cvta_generic_to_shared(sKp);

    const int dir = blockIdx.y;
    const float* K    = dir ? bw_k : fw_k;
    const float* bias = dir ? bw_b : fw_b;
    float* gy = g_ys[dir];

    const int b0  = blockIdx.x * 128;
    const int tid = threadIdx.x;
    const int tx  = tid & 31;        // hcol pair: hx = tx*2
    const int ty  = tid >> 5;        // row group: rows ty*8 .. ty*8+7
    const int hx  = tx * 2;
    const int r0  = ty * 8;

    // ---- prefetch x_0 and x_1 (cp.async) ----
    {
        int row = tid >> 2, seg = tid & 3;
        int b = b0 + row;
        int a = au[b];
        #pragma unroll
        for (int tt = 0; tt < 2; tt++) {
            int ts = dir ? ((tt < a) ? (a - 1 - tt) : tt) : tt;
            const float* src = g_x + ((size_t)b * 5 + ts) * 64 + seg * 16;
            unsigned dst = (unsigned)__cvta_generic_to_shared(xbuf + (tt & 1) * 8192 + row * 64 + seg * 16);
            #pragma unroll
            for (int q = 0; q < 4; q++) CP16(dst + q * 16, src + q * 4);
            CP_COMMIT();
        }
        if (seg == 0) sAu[row] = a;
    }

    // ---- load + plane-permute K ----
    // source float4 = K[kk][c4*4 .. c4*4+3]; gate g = c4>>4; h0 = (c4&15)*4
    // pairs p = h0/2 and p+1 within gate g; plane = g>>1; gpos = g&1
    #pragma unroll
    for (int it = 0; it < 16; it++) {
        int f = tid + it * 512;              // 8192 float4
        int kk = f >> 6, c4 = f & 63;
        float4 v = reinterpret_cast<const float4*>(K + (size_t)kk * 256)[c4];
        int g     = c4 >> 4;
        int p     = (c4 & 15) * 2;
        int plane = g >> 1;
        int gpos  = (g & 1) * 2;
        float2* d0 = reinterpret_cast<float2*>(&sKp[kk * 256 + plane * 128 + p * 4 + gpos]);
        float2* d1 = reinterpret_cast<float2*>(&sKp[kk * 256 + plane * 128 + (p + 1) * 4 + gpos]);
        *d0 = make_float2(v.x, v.y);
        *d1 = make_float2(v.z, v.w);
    }

    // ---- biases for this thread's 4 gates x 2 hcols ----
    float2 bg[4];
    #pragma unroll
    for (int g = 0; g < 4; g++)
        bg[g] = *reinterpret_cast<const float2*>(bias + g * 64 + hx);

    // ---- per-thread persistent cell state ----
    float2 cc[8];
    #pragma unroll
    for (int i = 0; i < 8; i++) cc[i] = make_float2(0.f, 0.f);

    const unsigned wbase = sKp_a + (unsigned)(tx * 4) * 4u;   // this thread's column offset

    for (int t = 0; t < 5; t++) {
        if (t < 4) { asm volatile("cp.async.wait_group 1;" ::: "memory"); }
        else       { asm volatile("cp.async.wait_group 0;" ::: "memory"); }
        __syncthreads();

        const float* xb = xbuf + (t & 1) * 8192;

        u64 acc[8][4];   // [row][gate: i,j,f,o]
        #pragma unroll
        for (int i = 0; i < 8; i++)
            #pragma unroll
            for (int g = 0; g < 4; g++) acc[i][g] = 0ull;

        // ---- GEMM, x half (k = 0..63), k-pair steps, weights fully hoisted ----
        #pragma unroll 2
        for (int k = 0; k < 64; k += 2) {
            u64 wi0, wj0, wf0, wo0, wi1, wj1, wf1, wo1;
            lds_v2u64(wi0, wj0, wbase + (unsigned)(k * 256) * 4u);
            lds_v2u64(wf0, wo0, wbase + (unsigned)(k * 256 + 128) * 4u);
            lds_v2u64(wi1, wj1, wbase + (unsigned)((k + 1) * 256) * 4u);
            lds_v2u64(wf1, wo1, wbase + (unsigned)((k + 1) * 256 + 128) * 4u);
            #pragma unroll
            for (int i = 0; i < 8; i++) {
                float2 a = *reinterpret_cast<const float2*>(&xb[(r0 + i) * 64 + k]);
                u64 sx = splat2(a.x), sy = splat2(a.y);
                ffma2(acc[i][0], sx, wi0); ffma2(acc[i][1], sx, wj0);
                ffma2(acc[i][2], sx, wf0); ffma2(acc[i][3], sx, wo0);
                ffma2(acc[i][0], sy, wi1); ffma2(acc[i][1], sy, wj1);
                ffma2(acc[i][2], sy, wf1); ffma2(acc[i][3], sy, wo1);
            }
        }

        // ---- GEMM, h half (k = 64..127), skipped on t == 0 ----
        if (t > 0) {
            #pragma unroll 2
            for (int k = 0; k < 64; k += 2) {
                u64 wi0, wj0, wf0, wo0, wi1, wj1, wf1, wo1;
                lds_v2u64(wi0, wj0, wbase + (unsigned)((k + 64) * 256) * 4u);
                lds_v2u64(wf0, wo0, wbase + (unsigned)((k + 64) * 256 + 128) * 4u);
                lds_v2u64(wi1, wj1, wbase + (unsigned)((k + 65) * 256) * 4u);
                lds_v2u64(wf1, wo1, wbase + (unsigned)((k + 65) * 256 + 128) * 4u);
                #pragma unroll
                for (int i = 0; i < 8; i++) {
                    float2 a = *reinterpret_cast<const float2*>(&sH[(r0 + i) * 66 + k]);
                    u64 sx = splat2(a.x), sy = splat2(a.y);
                    ffma2(acc[i][0], sx, wi0); ffma2(acc[i][1], sx, wj0);
                    ffma2(acc[i][2], sx, wf0); ffma2(acc[i][3], sx, wo0);
                    ffma2(acc[i][0], sy, wi1); ffma2(acc[i][1], sy, wj1);
                    ffma2(acc[i][2], sy, wf1); ffma2(acc[i][3], sy, wo1);
                }
            }
        }

        __syncthreads();   // all GEMM reads of sH / xbuf[t&1] complete

        // ---- prefetch x_{t+2} into the freed buffer ----
        if (t + 2 < 5) {
            int row = tid >> 2, seg = tid & 3;
            int b = b0 + row;
            int tt = t + 2;
            int a = sAu[row];
            int ts = dir ? ((tt < a) ? (a - 1 - tt) : tt) : tt;
            const float* src = g_x + ((size_t)b * 5 + ts) * 64 + seg * 16;
            unsigned dst = (unsigned)__cvta_generic_to_shared(xbuf + (tt & 1) * 8192 + row * 64 + seg * 16);
            #pragma unroll
            for (int q = 0; q < 4; q++) CP16(dst + q * 16, src + q * 4);
            CP_COMMIT();
        }

        // ---- gate epilogue ----
        #pragma unroll
        for (int i = 0; i < 8; i++) {
            int row = r0 + i;
            int a = sAu[row];
            bool valid = (t < a);
            float2 gi = unpack2(acc[i][0]);
            float2 gj = unpack2(acc[i][1]);
            float2 gf = unpack2(acc[i][2]);
            float2 go = unpack2(acc[i][3]);
            gi.x += bg[0].x; gi.y += bg[0].y;
            gj.x += bg[1].x; gj.y += bg[1].y;
            gf.x += bg[2].x; gf.y += bg[2].y;
            go.x += bg[3].x; go.y += bg[3].y;

            float2 hold = (t > 0) ? *reinterpret_cast<const float2*>(&sH[row * 66 + hx])
                                  : make_float2(0.f, 0.f);
            float2 cold = cc[i];

            float cnx = sig_f(gf.x + 1.f) * cold.x + sig_f(gi.x) * tanh_f(gj.x);
            float cny = sig_f(gf.y + 1.f) * cold.y + sig_f(gi.y) * tanh_f(gj.y);
            float hnx = sig_f(go.x) * tanh_f(cnx);
            float hny = sig_f(go.y) * tanh_f(cny);

            cc[i].x = valid ? cnx : cold.x;
            cc[i].y = valid ? cny : cold.y;
            float2 hw = make_float2(valid ? hnx : hold.x, valid ? hny : hold.y);
            *reinterpret_cast<float2*>(&sH[row * 66 + hx]) = hw;

            float2 yw = make_float2(valid ? hnx : 0.f, valid ? hny : 0.f);
            *reinterpret_cast<float2*>(gy + ((size_t)(b0 + row) * 5 + t) * 64 + hx) = yw;
        }
        // loop-top __syncthreads() publishes sH before next GEMM
    }
}

// =====================================================================================
// Kernel 3: LN over (T,2H) per batch + relu + conv dot + masked sum.  Warp per batch.
// =====================================================================================
__global__ __launch_bounds__(256)
void final_kernel(const float* __restrict__ mask,
                  const float* __restrict__ ln3g, const float* __restrict__ ln3b,
                  const float* __restrict__ convw, const float* __restrict__ convb,
                  const int* __restrict__ au, float* __restrict__ out)
{
    int b = blockIdx.x * 8 + (threadIdx.x >> 5);
    int lane = threadIdx.x & 31;
    int a = au[b];

    float vals[20];
    float s = 0.f, q = 0.f;
    #pragma unroll
    for (int t = 0; t < 5; t++) {
        int rt = (t < a) ? (a - 1 - t) : t;
        size_t fbase = ((size_t)b * 5 + t)  * 64;
        size_t bbase = ((size_t)b * 5 + rt) * 64;
        float v0 = g_ys[0][fbase + lane];
        float v1 = g_ys[0][fbase + lane + 32];
        float v2 = g_ys[1][bbase + lane];
        float v3 = g_ys[1][bbase + lane + 32];
        vals[t * 4 + 0] = v0; vals[t * 4 + 1] = v1;
        vals[t * 4 + 2] = v2; vals[t * 4 + 3] = v3;
        s += v0 + v1 + v2 + v3;
        q += v0 * v0 + v1 * v1 + v2 * v2 + v3 * v3;
    }
    #pragma unroll
    for (int o = 16; o; o >>= 1) { s += __shfl_xor_sync(~0u, s, o); q += __shfl_xor_sync(~0u, q, o); }
    float m = s * (1.f / 640.f);
    float var = q * (1.f / 640.f) - m * m;
    float rs = rsqrtf(var + EPSf);

    float g0 = ln3g[lane],      c0 = ln3b[lane],      w0 = convw[lane];
    float g1 = ln3g[lane + 32], c1 = ln3b[lane + 32], w1 = convw[lane + 32];
    float g2 = ln3g[lane + 64], c2 = ln3b[lane + 64], w2 = convw[lane + 64];
    float g3 = ln3g[lane + 96], c3 = ln3b[lane + 96], w3 = convw[lane + 96];

    float accq = 0.f, msum = 0.f;
    #pragma unroll
    for (int t = 0; t < 5; t++) {
        float p =
            fmaxf((vals[t*4+0] - m) * rs * g0 + c0, 0.f) * w0 +
            fmaxf((vals[t*4+1] - m) * rs * g1 + c1, 0.f) * w1 +
            fmaxf((vals[t*4+2] - m) * rs * g2 + c2, 0.f) * w2 +
            fmaxf((vals[t*4+3] - m) * rs * g3 + c3, 0.f) * w3;
        float mk = mask[(size_t)b * 5 + t];
        accq += p * mk;
        msum += mk;
    }
    #pragma unroll
    for (int o = 16; o; o >>= 1) accq += __shfl_xor_sync(~0u, accq, o);
    if (lane == 0) out[b] = accq + convb[0] * msum;
}

// =====================================================================================
extern "C" void kernel_launch(void* const* d_in, const int* in_sizes, int n_in,
                              void* d_out, int out_size)
{
    (void)in_sizes; (void)n_in; (void)out_size;
    const float* ud     = (const float*)d_in[0];
    const float* action = (const float*)d_in[1];
    const float* mask   = (const float*)d_in[2];
    const float* ln0g   = (const float*)d_in[3];
    const float* ln0b   = (const float*)d_in[4];
    const float* W1     = (const float*)d_in[5];
    const float* b1     = (const float*)d_in[6];
    const float* ln1g   = (const float*)d_in[7];
    const float* ln1b   = (const float*)d_in[8];
    const float* W2     = (const float*)d_in[9];
    const float* b2     = (const float*)d_in[10];
    const float* ln2g   = (const float*)d_in[11];
    const float* ln2b   = (const float*)d_in[12];
    const float* fw_k   = (const float*)d_in[13];
    const float* fw_b   = (const float*)d_in[14];
    const float* bw_k   = (const float*)d_in[15];
    const float* bw_b   = (const float*)d_in[16];
    const float* ln3g   = (const float*)d_in[17];
    const float* ln3b   = (const float*)d_in[18];
    const float* convw  = (const float*)d_in[19];
    const float* convb  = (const float*)d_in[20];
    const int*   au     = (const int*)d_in[21];

    const int MLP_SMEM  = (128*64 + 128*132 + 128*100 + 640) * 4;   // 154112 B
    const int LSTM_SMEM = 57728 * 4;                                // 230912 B

    cudaFuncSetAttribute(mlp_kernel,             cudaFuncAttributeMaxDynamicSharedMemorySize, MLP_SMEM);
    cudaFuncSetAttribute(lstm_persistent_kernel, cudaFuncAttributeMaxDynamicSharedMemorySize, LSTM_SMEM);

    mlp_kernel<<<BT / 128, 256, MLP_SMEM>>>(ud, action, ln0g, ln0b, W1, b1,
                                            ln1g, ln1b, W2, b2, ln2g, ln2b);

    lstm_persistent_kernel<<<dim3(Bn / 128, 2), 512, LSTM_SMEM>>>(fw_k, fw_b, bw_k, bw_b, au);

    final_kernel<<<Bn / 8, 256>>>(mask, ln3g, ln3b, convw, convb, au, (float*)d_out);
}

// round 6
// speedup vs baseline: 1.5031x; 1.5031x over previous
#include <cuda_runtime.h>
#include <math.h>

#define Bn   65536
#define Tn   5
#define OBSn 128
#define ACTn 32
#define Hn   64
#define BT   (Bn*Tn)
#define EPSf 1e-12f

typedef unsigned long long u64;

// ---------------- scratch (device globals; no allocation allowed) ----------------
__device__ float g_x[BT * Hn];          // MLP output, [B*T, 64]
__device__ float g_ys[2][BT * Hn];      // LSTM outputs per direction (bw in reversed-time order)
__device__ int   g_cnt[5];              // au histogram (bucket 0 = au==5 ... bucket 4 = au==1)
__device__ int   g_cursor[5];           // scatter cursors / prefix bases
__device__ int   g_perm[Bn];            // rows sorted by au descending

extern __shared__ float smem[];

// ---------------- packed f32x2 helpers (FFMA2 — ptxas never emits this itself) ----
__device__ __forceinline__ u64 splat2(float x) {
    u64 r; asm("mov.b64 %0, {%1, %1};" : "=l"(r) : "f"(x)); return r;
}
__device__ __forceinline__ void ffma2(u64& d, u64 a, u64 b) {
    asm("fma.rn.f32x2 %0, %1, %2, %0;" : "+l"(d) : "l"(a), "l"(b));
}
__device__ __forceinline__ void lds_v2u64(u64& a, u64& b, unsigned addr) {
    asm volatile("ld.shared.v2.u64 {%0, %1}, [%2];" : "=l"(a), "=l"(b) : "r"(addr));
}
__device__ __forceinline__ float2 unpack2(u64 v) {
    float2 f; asm("mov.b64 {%0, %1}, %2;" : "=f"(f.x), "=f"(f.y) : "l"(v)); return f;
}

// fast, accurate-enough (~1e-6) gate nonlinearities
__device__ __forceinline__ float sig_f(float x) {
    return __fdividef(1.f, 1.f + __expf(-x));
}
__device__ __forceinline__ float tanh_f(float x) {
    return __fdividef(2.f, 1.f + __expf(-2.f * x)) - 1.f;
}

#define CP16(dst, src) asm volatile("cp.async.ca.shared.global [%0], [%1], 16;" :: "r"(dst), "l"(src))
#define CP_COMMIT()    asm volatile("cp.async.commit_group;")

// =====================================================================================
// Sort-by-au kernels (counting sort, 5 buckets, descending au)
// =====================================================================================
__global__ void zero_cnt_kernel() {
    if (threadIdx.x < 5) g_cnt[threadIdx.x] = 0;
}

__global__ __launch_bounds__(512)
void hist_kernel(const int* __restrict__ au) {
    __shared__ int h[5];
    int tid = threadIdx.x;
    if (tid < 5) h[tid] = 0;
    __syncthreads();
    int i = blockIdx.x * 512 + tid;
    atomicAdd(&h[5 - au[i]], 1);
    __syncthreads();
    if (tid < 5) atomicAdd(&g_cnt[tid], h[tid]);
}

__global__ void prefix_kernel() {
    if (threadIdx.x == 0) {
        int s = 0;
        #pragma unroll
        for (int i = 0; i < 5; i++) { int c = g_cnt[i]; g_cursor[i] = s; s += c; }
    }
}

__global__ __launch_bounds__(512)
void scatter_kernel(const int* __restrict__ au) {
    int i = blockIdx.x * 512 + threadIdx.x;
    int lane = threadIdx.x & 31;
    int bkt = 5 - au[i];
    unsigned m = __match_any_sync(0xffffffffu, bkt);
    int leader = __ffs(m) - 1;
    int rank = __popc(m & ((1u << lane) - 1u));
    int base = 0;
    if (lane == leader) base = atomicAdd(&g_cursor[bkt], __popc(m));
    base = __shfl_sync(0xffffffffu, base, leader);
    g_perm[base + rank] = i;
}

// =====================================================================================
// Kernel 1: fused MLP.  Block = 64 rows of [B*T], 256 threads, 2 CTA/SM.
// Thread GEMM tile = 4 rows x 4 cols; A loaded as float4 per 4 k (R4 + fewer A LDS).
// =====================================================================================
__global__ __launch_bounds__(256)
void mlp_kernel(const float* __restrict__ ud, const float* __restrict__ act,
                const float* __restrict__ ln0g, const float* __restrict__ ln0b,
                const float* __restrict__ W1, const float* __restrict__ b1,
                const float* __restrict__ ln1g, const float* __restrict__ ln1b,
                const float* __restrict__ W2, const float* __restrict__ b2,
                const float* __restrict__ ln2g, const float* __restrict__ ln2b)
{
    float* sW  = smem;                 // 128*64 floats (W1, then W2)
    float* sX  = sW + 128 * 64;        // 64 * 132
    float* sX2 = sX + 64 * 132;        // 64 * 100
    float* sP  = sX2 + 64 * 100;       // 640

    const unsigned sW_a = (unsigned)__cvta_generic_to_shared(sW);

    const int tid = threadIdx.x;
    #pragma unroll
    for (int j = 0; j < 8; j++) {
        int f = tid + j * 256;
        reinterpret_cast<float4*>(sW)[f] = reinterpret_cast<const float4*>(W1)[f];
    }
    if (tid < 128) { sP[tid] = ln0g[tid]; sP[128 + tid] = ln0b[tid]; }
    if (tid < 64) {
        sP[256 + tid] = b1[tid];  sP[320 + tid] = ln1g[tid]; sP[384 + tid] = ln1b[tid];
        sP[448 + tid] = b2[tid];  sP[512 + tid] = ln2g[tid]; sP[576 + tid] = ln2b[tid];
    }

    const int r0 = blockIdx.x * 64;

    #pragma unroll
    for (int j = 0; j < 8; j++) {
        int f = tid + j * 256;
        int row = f >> 5, c4 = f & 31;
        float4 v = reinterpret_cast<const float4*>(ud + (size_t)(r0 + row) * 128)[c4];
        *reinterpret_cast<float4*>(&sX[row * 132 + c4 * 4]) = v;
    }
    #pragma unroll
    for (int j = 0; j < 2; j++) {
        int f = tid + j * 256;
        int row = f >> 3, c4 = f & 7;
        float4 v = reinterpret_cast<const float4*>(act + (size_t)(r0 + row) * 32)[c4];
        *reinterpret_cast<float4*>(&sX2[row * 100 + 64 + c4 * 4]) = v;
    }
    __syncthreads();

    const int w = tid >> 5, lane = tid & 31;

    // LN0 over 128 features (warp per row, 8 rows/warp)
    for (int rr = 0; rr < 8; rr++) {
        int row = w * 8 + rr;
        float v0 = sX[row * 132 + lane];
        float v1 = sX[row * 132 + lane + 32];
        float v2 = sX[row * 132 + lane + 64];
        float v3 = sX[row * 132 + lane + 96];
        float s = v0 + v1 + v2 + v3;
        float q = v0 * v0 + v1 * v1 + v2 * v2 + v3 * v3;
        #pragma unroll
        for (int o = 16; o; o >>= 1) { s += __shfl_xor_sync(~0u, s, o); q += __shfl_xor_sync(~0u, q, o); }
        float m = s * (1.f / 128.f);
        float var = q * (1.f / 128.f) - m * m;
        float rs = rsqrtf(var + EPSf);
        sX[row * 132 + lane]      = (v0 - m) * rs * sP[lane]      + sP[128 + lane];
        sX[row * 132 + lane + 32] = (v1 - m) * rs * sP[lane + 32] + sP[128 + lane + 32];
        sX[row * 132 + lane + 64] = (v2 - m) * rs * sP[lane + 64] + sP[128 + lane + 64];
        sX[row * 132 + lane + 96] = (v3 - m) * rs * sP[lane + 96] + sP[128 + lane + 96];
    }
    __syncthreads();

    const int ty = tid >> 4, tx = tid & 15;
    const int ry = ty * 4, cx = tx * 4;

    // GEMM1: (64x128)@(128x64), 4x4 tile, A as float4 per 4k
    u64 acc[4][2];
    #pragma unroll
    for (int i = 0; i < 4; i++) { acc[i][0] = 0ull; acc[i][1] = 0ull; }

    for (int k = 0; k < 128; k += 4) {
        float4 a4[4];
        #pragma unroll
        for (int i = 0; i < 4; i++)
            a4[i] = *reinterpret_cast<const float4*>(&sX[(ry + i) * 132 + k]);
        u64 w0[4], w1[4];
        #pragma unroll
        for (int kk = 0; kk < 4; kk++)
            lds_v2u64(w0[kk], w1[kk], sW_a + (unsigned)((k + kk) * 64 + cx) * 4u);
        #pragma unroll
        for (int kk = 0; kk < 4; kk++) {
            #pragma unroll
            for (int i = 0; i < 4; i++) {
                u64 s = splat2((&a4[i].x)[kk]);
                ffma2(acc[i][0], s, w0[kk]);
                ffma2(acc[i][1], s, w1[kk]);
            }
        }
    }
    __syncthreads();   // all sX + sW(W1) reads done

    // load W2 (96x64 = 1536 float4) into the W buffer
    #pragma unroll
    for (int j = 0; j < 6; j++) {
        int f = tid + j * 256;
        reinterpret_cast<float4*>(sW)[f] = reinterpret_cast<const float4*>(W2)[f];
    }

    #pragma unroll
    for (int i = 0; i < 4; i++) {
        float2 p0 = unpack2(acc[i][0]);
        float2 p1 = unpack2(acc[i][1]);
        float4 o;
        o.x = p0.x + sP[256 + cx + 0];
        o.y = p0.y + sP[256 + cx + 1];
        o.z = p1.x + sP[256 + cx + 2];
        o.w = p1.y + sP[256 + cx + 3];
        *reinterpret_cast<float4*>(&sX[(ry + i) * 132 + cx]) = o;
    }
    __syncthreads();

    // LN1 + relu -> sX2 cols [0,64)
    for (int rr = 0; rr < 8; rr++) {
        int row = w * 8 + rr;
        float v0 = sX[row * 132 + lane];
        float v1 = sX[row * 132 + lane + 32];
        float s = v0 + v1, q = v0 * v0 + v1 * v1;
        #pragma unroll
        for (int o = 16; o; o >>= 1) { s += __shfl_xor_sync(~0u, s, o); q += __shfl_xor_sync(~0u, q, o); }
        float m = s * (1.f / 64.f);
        float var = q * (1.f / 64.f) - m * m;
        float rs = rsqrtf(var + EPSf);
        float y0 = (v0 - m) * rs * sP[320 + lane]      + sP[384 + lane];
        float y1 = (v1 - m) * rs * sP[320 + lane + 32] + sP[384 + lane + 32];
        sX2[row * 100 + lane]      = fmaxf(y0, 0.f);
        sX2[row * 100 + lane + 32] = fmaxf(y1, 0.f);
    }
    __syncthreads();   // W2 + sX2 ready

    // GEMM2: (64x96)@(96x64)
    u64 acc2[4][2];
    #pragma unroll
    for (int i = 0; i < 4; i++) { acc2[i][0] = 0ull; acc2[i][1] = 0ull; }

    for (int k = 0; k < 96; k += 4) {
        float4 a4[4];
        #pragma unroll
        for (int i = 0; i < 4; i++)
            a4[i] = *reinterpret_cast<const float4*>(&sX2[(ry + i) * 100 + k]);
        u64 w0[4], w1[4];
        #pragma unroll
        for (int kk = 0; kk < 4; kk++)
            lds_v2u64(w0[kk], w1[kk], sW_a + (unsigned)((k + kk) * 64 + cx) * 4u);
        #pragma unroll
        for (int kk = 0; kk < 4; kk++) {
            #pragma unroll
            for (int i = 0; i < 4; i++) {
                u64 s = splat2((&a4[i].x)[kk]);
                ffma2(acc2[i][0], s, w0[kk]);
                ffma2(acc2[i][1], s, w1[kk]);
            }
        }
    }
    __syncthreads();

    #pragma unroll
    for (int i = 0; i < 4; i++) {
        float2 p0 = unpack2(acc2[i][0]);
        float2 p1 = unpack2(acc2[i][1]);
        float4 o;
        o.x = p0.x + sP[448 + cx + 0];
        o.y = p0.y + sP[448 + cx + 1];
        o.z = p1.x + sP[448 + cx + 2];
        o.w = p1.y + sP[448 + cx + 3];
        *reinterpret_cast<float4*>(&sX[(ry + i) * 132 + cx]) = o;
    }
    __syncthreads();

    // LN2 + relu -> global g_x
    for (int rr = 0; rr < 8; rr++) {
        int row = w * 8 + rr;
        float v0 = sX[row * 132 + lane];
        float v1 = sX[row * 132 + lane + 32];
        float s = v0 + v1, q = v0 * v0 + v1 * v1;
        #pragma unroll
        for (int o = 16; o; o >>= 1) { s += __shfl_xor_sync(~0u, s, o); q += __shfl_xor_sync(~0u, q, o); }
        float m = s * (1.f / 64.f);
        float var = q * (1.f / 64.f) - m * m;
        float rs = rsqrtf(var + EPSf);
        float y0 = (v0 - m) * rs * sP[512 + lane]      + sP[576 + lane];
        float y1 = (v1 - m) * rs * sP[512 + lane + 32] + sP[576 + lane + 32];
        size_t base = (size_t)(r0 + row) * 64;
        g_x[base + lane]      = fmaxf(y0, 0.f);
        g_x[base + lane + 32] = fmaxf(y1, 0.f);
    }
}

// =====================================================================================
// Kernel 2: persistent bidirectional LSTM over au-SORTED rows.
//   grid = (512, 2): 128 sorted rows per CTA, blockIdx.y = direction. 512 threads.
//   CTA loops only t < mx (= max au in CTA, first sorted row). ~40% work skipped.
// =====================================================================================
__global__ __launch_bounds__(512, 1)
void lstm_persistent_kernel(const float* __restrict__ fw_k, const float* __restrict__ fw_b,
                            const float* __restrict__ bw_k, const float* __restrict__ bw_b,
                            const int* __restrict__ au)
{
    float* sKp  = smem;                  // 32768
    float* xbuf = smem + 32768;          // 2 x 128 x 64
    float* sH   = smem + 49152;          // 128 x 66
    int*   sAu  = (int*)(smem + 57600);  // 128
    int*   sPb  = sAu + 128;             // 128 (permuted batch index per row)

    const unsigned sKp_a = (unsigned)__cvta_generic_to_shared(sKp);

    const int dir = blockIdx.y;
    const float* K    = dir ? bw_k : fw_k;
    const float* bias = dir ? bw_b : fw_b;
    float* gy = g_ys[dir];

    const int b0  = blockIdx.x * 128;
    const int tid = threadIdx.x;
    const int tx  = tid & 31;
    const int ty  = tid >> 5;
    const int hx  = tx * 2;
    const int r0  = ty * 8;

    const int mx = au[g_perm[b0]];       // sorted descending -> max au in this CTA

    // ---- prefetch x_0 and x_1 (cp.async) via permuted rows ----
    {
        int row = tid >> 2, seg = tid & 3;
        int pb = g_perm[b0 + row];
        int a = au[pb];
        #pragma unroll
        for (int tt = 0; tt < 2; tt++) {
            int ts = dir ? ((tt < a) ? (a - 1 - tt) : tt) : tt;
            const float* src = g_x + ((size_t)pb * 5 + ts) * 64 + seg * 16;
            unsigned dst = (unsigned)__cvta_generic_to_shared(xbuf + (tt & 1) * 8192 + row * 64 + seg * 16);
            #pragma unroll
            for (int q = 0; q < 4; q++) CP16(dst + q * 16, src + q * 4);
            CP_COMMIT();
        }
        if (seg == 0) { sAu[row] = a; sPb[row] = pb; }
    }

    // ---- load + plane-permute K ----
    #pragma unroll
    for (int it = 0; it < 16; it++) {
        int f = tid + it * 512;
        int kk = f >> 6, c4 = f & 63;
        float4 v = reinterpret_cast<const float4*>(K + (size_t)kk * 256)[c4];
        int g     = c4 >> 4;
        int p     = (c4 & 15) * 2;
        int plane = g >> 1;
        int gpos  = (g & 1) * 2;
        float2* d0 = reinterpret_cast<float2*>(&sKp[kk * 256 + plane * 128 + p * 4 + gpos]);
        float2* d1 = reinterpret_cast<float2*>(&sKp[kk * 256 + plane * 128 + (p + 1) * 4 + gpos]);
        *d0 = make_float2(v.x, v.y);
        *d1 = make_float2(v.z, v.w);
    }

    float2 bg[4];
    #pragma unroll
    for (int g = 0; g < 4; g++)
        bg[g] = *reinterpret_cast<const float2*>(bias + g * 64 + hx);

    float2 cc[8];
    #pragma unroll
    for (int i = 0; i < 8; i++) cc[i] = make_float2(0.f, 0.f);

    const unsigned wbase = sKp_a + (unsigned)(tx * 4) * 4u;

    for (int t = 0; t < mx; t++) {
        asm volatile("cp.async.wait_group 1;" ::: "memory");
        __syncthreads();

        const float* xb = xbuf + (t & 1) * 8192;

        u64 acc[8][4];
        #pragma unroll
        for (int i = 0; i < 8; i++)
            #pragma unroll
            for (int g = 0; g < 4; g++) acc[i][g] = 0ull;

        // ---- GEMM, x half ----
        #pragma unroll 2
        for (int k = 0; k < 64; k += 2) {
            u64 wi0, wj0, wf0, wo0, wi1, wj1, wf1, wo1;
            lds_v2u64(wi0, wj0, wbase + (unsigned)(k * 256) * 4u);
            lds_v2u64(wf0, wo0, wbase + (unsigned)(k * 256 + 128) * 4u);
            lds_v2u64(wi1, wj1, wbase + (unsigned)((k + 1) * 256) * 4u);
            lds_v2u64(wf1, wo1, wbase + (unsigned)((k + 1) * 256 + 128) * 4u);
            #pragma unroll
            for (int i = 0; i < 8; i++) {
                float2 a = *reinterpret_cast<const float2*>(&xb[(r0 + i) * 64 + k]);
                u64 sx = splat2(a.x), sy = splat2(a.y);
                ffma2(acc[i][0], sx, wi0); ffma2(acc[i][1], sx, wj0);
                ffma2(acc[i][2], sx, wf0); ffma2(acc[i][3], sx, wo0);
                ffma2(acc[i][0], sy, wi1); ffma2(acc[i][1], sy, wj1);
                ffma2(acc[i][2], sy, wf1); ffma2(acc[i][3], sy, wo1);
            }
        }

        // ---- GEMM, h half (skipped on t == 0) ----
        if (t > 0) {
            #pragma unroll 2
            for (int k = 0; k < 64; k += 2) {
                u64 wi0, wj0, wf0, wo0, wi1, wj1, wf1, wo1;
                lds_v2u64(wi0, wj0, wbase + (unsigned)((k + 64) * 256) * 4u);
                lds_v2u64(wf0, wo0, wbase + (unsigned)((k + 64) * 256 + 128) * 4u);
                lds_v2u64(wi1, wj1, wbase + (unsigned)((k + 65) * 256) * 4u);
                lds_v2u64(wf1, wo1, wbase + (unsigned)((k + 65) * 256 + 128) * 4u);
                #pragma unroll
                for (int i = 0; i < 8; i++) {
                    float2 a = *reinterpret_cast<const float2*>(&sH[(r0 + i) * 66 + k]);
                    u64 sx = splat2(a.x), sy = splat2(a.y);
                    ffma2(acc[i][0], sx, wi0); ffma2(acc[i][1], sx, wj0);
                    ffma2(acc[i][2], sx, wf0); ffma2(acc[i][3], sx, wo0);
                    ffma2(acc[i][0], sy, wi1); ffma2(acc[i][1], sy, wj1);
                    ffma2(acc[i][2], sy, wf1); ffma2(acc[i][3], sy, wo1);
                }
            }
        }

        __syncthreads();

        // ---- prefetch x_{t+2} if that step will run ----
        if (t + 2 < mx) {
            int row = tid >> 2, seg = tid & 3;
            int pb = sPb[row];
            int tt = t + 2;
            int a = sAu[row];
            int ts = dir ? ((tt < a) ? (a - 1 - tt) : tt) : tt;
            const float* src = g_x + ((size_t)pb * 5 + ts) * 64 + seg * 16;
            unsigned dst = (unsigned)__cvta_generic_to_shared(xbuf + (tt & 1) * 8192 + row * 64 + seg * 16);
            #pragma unroll
            for (int q = 0; q < 4; q++) CP16(dst + q * 16, src + q * 4);
            CP_COMMIT();
        }

        // ---- gate epilogue ----
        #pragma unroll
        for (int i = 0; i < 8; i++) {
            int row = r0 + i;
            int a = sAu[row];
            bool valid = (t < a);
            float2 gi = unpack2(acc[i][0]);
            float2 gj = unpack2(acc[i][1]);
            float2 gf = unpack2(acc[i][2]);
            float2 go = unpack2(acc[i][3]);
            gi.x += bg[0].x; gi.y += bg[0].y;
            gj.x += bg[1].x; gj.y += bg[1].y;
            gf.x += bg[2].x; gf.y += bg[2].y;
            go.x += bg[3].x; go.y += bg[3].y;

            float2 hold = (t > 0) ? *reinterpret_cast<const float2*>(&sH[row * 66 + hx])
                                  : make_float2(0.f, 0.f);
            float2 cold = cc[i];

            float cnx = sig_f(gf.x + 1.f) * cold.x + sig_f(gi.x) * tanh_f(gj.x);
            float cny = sig_f(gf.y + 1.f) * cold.y + sig_f(gi.y) * tanh_f(gj.y);
            float hnx = sig_f(go.x) * tanh_f(cnx);
            float hny = sig_f(go.y) * tanh_f(cny);

            cc[i].x = valid ? cnx : cold.x;
            cc[i].y = valid ? cny : cold.y;
            float2 hw = make_float2(valid ? hnx : hold.x, valid ? hny : hold.y);
            *reinterpret_cast<float2*>(&sH[row * 66 + hx]) = hw;

            float2 yw = make_float2(valid ? hnx : 0.f, valid ? hny : 0.f);
            *reinterpret_cast<float2*>(gy + ((size_t)sPb[row] * 5 + t) * 64 + hx) = yw;
        }
    }
    asm volatile("cp.async.wait_group 0;" ::: "memory");
}

// =====================================================================================
// Kernel 3: LN over (T,2H) + relu + conv dot + masked sum. Warp per batch.
// Substitutes exact zeros for t >= au (those ys slots are never written now).
// =====================================================================================
__global__ __launch_bounds__(256)
void final_kernel(const float* __restrict__ mask,
                  const float* __restrict__ ln3g, const float* __restrict__ ln3b,
                  const float* __restrict__ convw, const float* __restrict__ convb,
                  const int* __restrict__ au, float* __restrict__ out)
{
    int b = blockIdx.x * 8 + (threadIdx.x >> 5);
    int lane = threadIdx.x & 31;
    int a = au[b];

    float vals[20];
    float s = 0.f, q = 0.f;
    #pragma unroll
    for (int t = 0; t < 5; t++) {
        float v0 = 0.f, v1 = 0.f, v2 = 0.f, v3 = 0.f;
        if (t < a) {
            int rt = a - 1 - t;
            size_t fbase = ((size_t)b * 5 + t)  * 64;
            size_t bbase = ((size_t)b * 5 + rt) * 64;
            v0 = g_ys[0][fbase + lane];
            v1 = g_ys[0][fbase + lane + 32];
            v2 = g_ys[1][bbase + lane];
            v3 = g_ys[1][bbase + lane + 32];
        }
        vals[t * 4 + 0] = v0; vals[t * 4 + 1] = v1;
        vals[t * 4 + 2] = v2; vals[t * 4 + 3] = v3;
        s += v0 + v1 + v2 + v3;
        q += v0 * v0 + v1 * v1 + v2 * v2 + v3 * v3;
    }
    #pragma unroll
    for (int o = 16; o; o >>= 1) { s += __shfl_xor_sync(~0u, s, o); q += __shfl_xor_sync(~0u, q, o); }
    float m = s * (1.f / 640.f);
    float var = q * (1.f / 640.f) - m * m;
    float rs = rsqrtf(var + EPSf);

    float g0 = ln3g[lane],      c0 = ln3b[lane],      w0 = convw[lane];
    float g1 = ln3g[lane + 32], c1 = ln3b[lane + 32], w1 = convw[lane + 32];
    float g2 = ln3g[lane + 64], c2 = ln3b[lane + 64], w2 = convw[lane + 64];
    float g3 = ln3g[lane + 96], c3 = ln3b[lane + 96], w3 = convw[lane + 96];

    float accq = 0.f, msum = 0.f;
    #pragma unroll
    for (int t = 0; t < 5; t++) {
        float p =
            fmaxf((vals[t*4+0] - m) * rs * g0 + c0, 0.f) * w0 +
            fmaxf((vals[t*4+1] - m) * rs * g1 + c1, 0.f) * w1 +
            fmaxf((vals[t*4+2] - m) * rs * g2 + c2, 0.f) * w2 +
            fmaxf((vals[t*4+3] - m) * rs * g3 + c3, 0.f) * w3;
        float mk = mask[(size_t)b * 5 + t];
        accq += p * mk;
        msum += mk;
    }
    #pragma unroll
    for (int o = 16; o; o >>= 1) accq += __shfl_xor_sync(~0u, accq, o);
    if (lane == 0) out[b] = accq + convb[0] * msum;
}

// =====================================================================================
extern "C" void kernel_launch(void* const* d_in, const int* in_sizes, int n_in,
                              void* d_out, int out_size)
{
    (void)in_sizes; (void)n_in; (void)out_size;
    const float* ud     = (const float*)d_in[0];
    const float* action = (const float*)d_in[1];
    const float* mask   = (const float*)d_in[2];
    const float* ln0g   = (const float*)d_in[3];
    const float* ln0b   = (const float*)d_in[4];
    const float* W1     = (const float*)d_in[5];
    const float* b1     = (const float*)d_in[6];
    const float* ln1g   = (const float*)d_in[7];
    const float* ln1b   = (const float*)d_in[8];
    const float* W2     = (const float*)d_in[9];
    const float* b2     = (const float*)d_in[10];
    const float* ln2g   = (const float*)d_in[11];
    const float* ln2b   = (const float*)d_in[12];
    const float* fw_k   = (const float*)d_in[13];
    const float* fw_b   = (const float*)d_in[14];
    const float* bw_k   = (const float*)d_in[15];
    const float* bw_b   = (const float*)d_in[16];
    const float* ln3g   = (const float*)d_in[17];
    const float* ln3b   = (const float*)d_in[18];
    const float* convw  = (const float*)d_in[19];
    const float* convb  = (const float*)d_in[20];
    const int*   au     = (const int*)d_in[21];

    const int MLP_SMEM  = (128*64 + 64*132 + 64*100 + 640) * 4;   // 94720 B
    const int LSTM_SMEM = (57728 + 256) * 4;                      // 231936 B

    cudaFuncSetAttribute(mlp_kernel,             cudaFuncAttributeMaxDynamicSharedMemorySize, MLP_SMEM);
    cudaFuncSetAttribute(lstm_persistent_kernel, cudaFuncAttributeMaxDynamicSharedMemorySize, LSTM_SMEM);

    // sort rows by au (descending)
    zero_cnt_kernel<<<1, 32>>>();
    hist_kernel<<<Bn / 512, 512>>>(au);
    prefix_kernel<<<1, 32>>>();
    scatter_kernel<<<Bn / 512, 512>>>(au);

    mlp_kernel<<<BT / 64, 256, MLP_SMEM>>>(ud, action, ln0g, ln0b, W1, b1,
                                           ln1g, ln1b, W2, b2, ln2g, ln2b);

    lstm_persistent_kernel<<<dim3(Bn / 128, 2), 512, LSTM_SMEM>>>(fw_k, fw_b, bw_k, bw_b, au);

    final_kernel<<<Bn / 8, 256>>>(mask, ln3g, ln3b, convw, convb, au, (float*)d_out);
}

// round 7
// speedup vs baseline: 1.5043x; 1.0008x over previous
#include <cuda_runtime.h>
#include <math.h>

#define Bn   65536
#define Tn   5
#define OBSn 128
#define ACTn 32
#define Hn   64
#define BT   (Bn*Tn)
#define EPSf 1e-12f

typedef unsigned long long u64;

// ---------------- scratch (device globals; no allocation allowed) ----------------
__device__ float g_x[BT * Hn];          // MLP output, [B*T, 64]
__device__ float g_ys[2][BT * Hn];      // LSTM outputs per direction (bw in reversed-time order)
__device__ int   g_cnt[5];              // au histogram (bucket 0 = au==5 ... bucket 4 = au==1)
__device__ int   g_cursor[5];           // scatter cursors / prefix bases
__device__ int   g_perm[Bn];            // rows sorted by au descending

extern __shared__ float smem[];

// ---------------- packed f32x2 helpers (FFMA2 — ptxas never emits this itself) ----
__device__ __forceinline__ u64 splat2(float x) {
    u64 r; asm("mov.b64 %0, {%1, %1};" : "=l"(r) : "f"(x)); return r;
}
__device__ __forceinline__ void ffma2(u64& d, u64 a, u64 b) {
    asm("fma.rn.f32x2 %0, %1, %2, %0;" : "+l"(d) : "l"(a), "l"(b));
}
__device__ __forceinline__ void lds_v2u64(u64& a, u64& b, unsigned addr) {
    asm volatile("ld.shared.v2.u64 {%0, %1}, [%2];" : "=l"(a), "=l"(b) : "r"(addr));
}
__device__ __forceinline__ float2 unpack2(u64 v) {
    float2 f; asm("mov.b64 {%0, %1}, %2;" : "=f"(f.x), "=f"(f.y) : "l"(v)); return f;
}

// fast, accurate-enough (~1e-6) gate nonlinearities
__device__ __forceinline__ float sig_f(float x) {
    return __fdividef(1.f, 1.f + __expf(-x));
}
__device__ __forceinline__ float tanh_f(float x) {
    return __fdividef(2.f, 1.f + __expf(-2.f * x)) - 1.f;
}

#define CP16(dst, src) asm volatile("cp.async.ca.shared.global [%0], [%1], 16;" :: "r"(dst), "l"(src))
#define CP_COMMIT()    asm volatile("cp.async.commit_group;")

// =====================================================================================
// Sort-by-au kernels (counting sort, 5 buckets, descending au)
// =====================================================================================
__global__ void zero_cnt_kernel() {
    if (threadIdx.x < 5) g_cnt[threadIdx.x] = 0;
}

__global__ __launch_bounds__(512)
void hist_kernel(const int* __restrict__ au) {
    __shared__ int h[5];
    int tid = threadIdx.x;
    if (tid < 5) h[tid] = 0;
    __syncthreads();
    int i = blockIdx.x * 512 + tid;
    atomicAdd(&h[5 - au[i]], 1);
    __syncthreads();
    if (tid < 5) atomicAdd(&g_cnt[tid], h[tid]);
}

__global__ void prefix_kernel() {
    if (threadIdx.x == 0) {
        int s = 0;
        #pragma unroll
        for (int i = 0; i < 5; i++) { int c = g_cnt[i]; g_cursor[i] = s; s += c; }
    }
}

__global__ __launch_bounds__(512)
void scatter_kernel(const int* __restrict__ au) {
    int i = blockIdx.x * 512 + threadIdx.x;
    int lane = threadIdx.x & 31;
    int bkt = 5 - au[i];
    unsigned m = __match_any_sync(0xffffffffu, bkt);
    int leader = __ffs(m) - 1;
    int rank = __popc(m & ((1u << lane) - 1u));
    int base = 0;
    if (lane == leader) base = atomicAdd(&g_cursor[bkt], __popc(m));
    base = __shfl_sync(0xffffffffu, base, leader);
    g_perm[base + rank] = i;
}

// =====================================================================================
// Kernel 1: fused MLP.  Block = 64 rows of [B*T], 256 threads, 2 CTA/SM.
// Thread GEMM tile = 4 rows x 4 cols; A loaded as float4 per 4 k (R4 + fewer A LDS).
// =====================================================================================
__global__ __launch_bounds__(256)
void mlp_kernel(const float* __restrict__ ud, const float* __restrict__ act,
                const float* __restrict__ ln0g, const float* __restrict__ ln0b,
                const float* __restrict__ W1, const float* __restrict__ b1,
                const float* __restrict__ ln1g, const float* __restrict__ ln1b,
                const float* __restrict__ W2, const float* __restrict__ b2,
                const float* __restrict__ ln2g, const float* __restrict__ ln2b)
{
    float* sW  = smem;                 // 128*64 floats (W1, then W2)
    float* sX  = sW + 128 * 64;        // 64 * 132
    float* sX2 = sX + 64 * 132;        // 64 * 100
    float* sP  = sX2 + 64 * 100;       // 640

    const unsigned sW_a = (unsigned)__cvta_generic_to_shared(sW);

    const int tid = threadIdx.x;
    #pragma unroll
    for (int j = 0; j < 8; j++) {
        int f = tid + j * 256;
        reinterpret_cast<float4*>(sW)[f] = reinterpret_cast<const float4*>(W1)[f];
    }
    if (tid < 128) { sP[tid] = ln0g[tid]; sP[128 + tid] = ln0b[tid]; }
    if (tid < 64) {
        sP[256 + tid] = b1[tid];  sP[320 + tid] = ln1g[tid]; sP[384 + tid] = ln1b[tid];
        sP[448 + tid] = b2[tid];  sP[512 + tid] = ln2g[tid]; sP[576 + tid] = ln2b[tid];
    }

    const int r0 = blockIdx.x * 64;

    #pragma unroll
    for (int j = 0; j < 8; j++) {
        int f = tid + j * 256;
        int row = f >> 5, c4 = f & 31;
        float4 v = reinterpret_cast<const float4*>(ud + (size_t)(r0 + row) * 128)[c4];
        *reinterpret_cast<float4*>(&sX[row * 132 + c4 * 4]) = v;
    }
    #pragma unroll
    for (int j = 0; j < 2; j++) {
        int f = tid + j * 256;
        int row = f >> 3, c4 = f & 7;
        float4 v = reinterpret_cast<const float4*>(act + (size_t)(r0 + row) * 32)[c4];
        *reinterpret_cast<float4*>(&sX2[row * 100 + 64 + c4 * 4]) = v;
    }
    __syncthreads();

    const int w = tid >> 5, lane = tid & 31;

    // LN0 over 128 features (warp per row, 8 rows/warp)
    for (int rr = 0; rr < 8; rr++) {
        int row = w * 8 + rr;
        float v0 = sX[row * 132 + lane];
        float v1 = sX[row * 132 + lane + 32];
        float v2 = sX[row * 132 + lane + 64];
        float v3 = sX[row * 132 + lane + 96];
        float s = v0 + v1 + v2 + v3;
        float q = v0 * v0 + v1 * v1 + v2 * v2 + v3 * v3;
        #pragma unroll
        for (int o = 16; o; o >>= 1) { s += __shfl_xor_sync(~0u, s, o); q += __shfl_xor_sync(~0u, q, o); }
        float m = s * (1.f / 128.f);
        float var = q * (1.f / 128.f) - m * m;
        float rs = rsqrtf(var + EPSf);
        sX[row * 132 + lane]      = (v0 - m) * rs * sP[lane]      + sP[128 + lane];
        sX[row * 132 + lane + 32] = (v1 - m) * rs * sP[lane + 32] + sP[128 + lane + 32];
        sX[row * 132 + lane + 64] = (v2 - m) * rs * sP[lane + 64] + sP[128 + lane + 64];
        sX[row * 132 + lane + 96] = (v3 - m) * rs * sP[lane + 96] + sP[128 + lane + 96];
    }
    __syncthreads();

    const int ty = tid >> 4, tx = tid & 15;
    const int ry = ty * 4, cx = tx * 4;

    // GEMM1: (64x128)@(128x64), 4x4 tile, A as float4 per 4k
    u64 acc[4][2];
    #pragma unroll
    for (int i = 0; i < 4; i++) { acc[i][0] = 0ull; acc[i][1] = 0ull; }

    for (int k = 0; k < 128; k += 4) {
        float4 a4[4];
        #pragma unroll
        for (int i = 0; i < 4; i++)
            a4[i] = *reinterpret_cast<const float4*>(&sX[(ry + i) * 132 + k]);
        u64 w0[4], w1[4];
        #pragma unroll
        for (int kk = 0; kk < 4; kk++)
            lds_v2u64(w0[kk], w1[kk], sW_a + (unsigned)((k + kk) * 64 + cx) * 4u);
        #pragma unroll
        for (int kk = 0; kk < 4; kk++) {
            #pragma unroll
            for (int i = 0; i < 4; i++) {
                u64 s = splat2((&a4[i].x)[kk]);
                ffma2(acc[i][0], s, w0[kk]);
                ffma2(acc[i][1], s, w1[kk]);
            }
        }
    }
    __syncthreads();   // all sX + sW(W1) reads done

    // load W2 (96x64 = 1536 float4) into the W buffer
    #pragma unroll
    for (int j = 0; j < 6; j++) {
        int f = tid + j * 256;
        reinterpret_cast<float4*>(sW)[f] = reinterpret_cast<const float4*>(W2)[f];
    }

    #pragma unroll
    for (int i = 0; i < 4; i++) {
        float2 p0 = unpack2(acc[i][0]);
        float2 p1 = unpack2(acc[i][1]);
        float4 o;
        o.x = p0.x + sP[256 + cx + 0];
        o.y = p0.y + sP[256 + cx + 1];
        o.z = p1.x + sP[256 + cx + 2];
        o.w = p1.y + sP[256 + cx + 3];
        *reinterpret_cast<float4*>(&sX[(ry + i) * 132 + cx]) = o;
    }
    __syncthreads();

    // LN1 + relu -> sX2 cols [0,64)
    for (int rr = 0; rr < 8; rr++) {
        int row = w * 8 + rr;
        float v0 = sX[row * 132 + lane];
        float v1 = sX[row * 132 + lane + 32];
        float s = v0 + v1, q = v0 * v0 + v1 * v1;
        #pragma unroll
        for (int o = 16; o; o >>= 1) { s += __shfl_xor_sync(~0u, s, o); q += __shfl_xor_sync(~0u, q, o); }
        float m = s * (1.f / 64.f);
        float var = q * (1.f / 64.f) - m * m;
        float rs = rsqrtf(var + EPSf);
        float y0 = (v0 - m) * rs * sP[320 + lane]      + sP[384 + lane];
        float y1 = (v1 - m) * rs * sP[320 + lane + 32] + sP[384 + lane + 32];
        sX2[row * 100 + lane]      = fmaxf(y0, 0.f);
        sX2[row * 100 + lane + 32] = fmaxf(y1, 0.f);
    }
    __syncthreads();   // W2 + sX2 ready

    // GEMM2: (64x96)@(96x64)
    u64 acc2[4][2];
    #pragma unroll
    for (int i = 0; i < 4; i++) { acc2[i][0] = 0ull; acc2[i][1] = 0ull; }

    for (int k = 0; k < 96; k += 4) {
        float4 a4[4];
        #pragma unroll
        for (int i = 0; i < 4; i++)
            a4[i] = *reinterpret_cast<const float4*>(&sX2[(ry + i) * 100 + k]);
        u64 w0[4], w1[4];
        #pragma unroll
        for (int kk = 0; kk < 4; kk++)
            lds_v2u64(w0[kk], w1[kk], sW_a + (unsigned)((k + kk) * 64 + cx) * 4u);
        #pragma unroll
        for (int kk = 0; kk < 4; kk++) {
            #pragma unroll
            for (int i = 0; i < 4; i++) {
                u64 s = splat2((&a4[i].x)[kk]);
                ffma2(acc2[i][0], s, w0[kk]);
                ffma2(acc2[i][1], s, w1[kk]);
            }
        }
    }
    __syncthreads();

    #pragma unroll
    for (int i = 0; i < 4; i++) {
        float2 p0 = unpack2(acc2[i][0]);
        float2 p1 = unpack2(acc2[i][1]);
        float4 o;
        o.x = p0.x + sP[448 + cx + 0];
        o.y = p0.y + sP[448 + cx + 1];
        o.z = p1.x + sP[448 + cx + 2];
        o.w = p1.y + sP[448 + cx + 3];
        *reinterpret_cast<float4*>(&sX[(ry + i) * 132 + cx]) = o;
    }
    __syncthreads();

    // LN2 + relu -> global g_x
    for (int rr = 0; rr < 8; rr++) {
        int row = w * 8 + rr;
        float v0 = sX[row * 132 + lane];
        float v1 = sX[row * 132 + lane + 32];
        float s = v0 + v1, q = v0 * v0 + v1 * v1;
        #pragma unroll
        for (int o = 16; o; o >>= 1) { s += __shfl_xor_sync(~0u, s, o); q += __shfl_xor_sync(~0u, q, o); }
        float m = s * (1.f / 64.f);
        float var = q * (1.f / 64.f) - m * m;
        float rs = rsqrtf(var + EPSf);
        float y0 = (v0 - m) * rs * sP[512 + lane]      + sP[576 + lane];
        float y1 = (v1 - m) * rs * sP[512 + lane + 32] + sP[576 + lane + 32];
        size_t base = (size_t)(r0 + row) * 64;
        g_x[base + lane]      = fmaxf(y0, 0.f);
        g_x[base + lane + 32] = fmaxf(y1, 0.f);
    }
}

// =====================================================================================
// Kernel 2: persistent bidirectional LSTM over au-SORTED rows.
//   grid = (512, 2): 128 sorted rows per CTA, blockIdx.y = direction. 512 threads.
//   CTA loops only t < mx (= max au in CTA, first sorted row). ~40% work skipped.
// =====================================================================================
__global__ __launch_bounds__(512, 1)
void lstm_persistent_kernel(const float* __restrict__ fw_k, const float* __restrict__ fw_b,
                            const float* __restrict__ bw_k, const float* __restrict__ bw_b,
                            const int* __restrict__ au)
{
    float* sKp  = smem;                  // 32768
    float* xbuf = smem + 32768;          // 2 x 128 x 64
    float* sH   = smem + 49152;          // 128 x 66
    int*   sAu  = (int*)(smem + 57600);  // 128
    int*   sPb  = sAu + 128;             // 128 (permuted batch index per row)

    const unsigned sKp_a = (unsigned)__cvta_generic_to_shared(sKp);

    const int dir = blockIdx.y;
    const float* K    = dir ? bw_k : fw_k;
    const float* bias = dir ? bw_b : fw_b;
    float* gy = g_ys[dir];

    const int b0  = blockIdx.x * 128;
    const int tid = threadIdx.x;
    const int tx  = tid & 31;
    const int ty  = tid >> 5;
    const int hx  = tx * 2;
    const int r0  = ty * 8;

    const int mx = au[g_perm[b0]];       // sorted descending -> max au in this CTA

    // ---- prefetch x_0 and x_1 (cp.async) via permuted rows ----
    {
        int row = tid >> 2, seg = tid & 3;
        int pb = g_perm[b0 + row];
        int a = au[pb];
        #pragma unroll
        for (int tt = 0; tt < 2; tt++) {
            int ts = dir ? ((tt < a) ? (a - 1 - tt) : tt) : tt;
            const float* src = g_x + ((size_t)pb * 5 + ts) * 64 + seg * 16;
            unsigned dst = (unsigned)__cvta_generic_to_shared(xbuf + (tt & 1) * 8192 + row * 64 + seg * 16);
            #pragma unroll
            for (int q = 0; q < 4; q++) CP16(dst + q * 16, src + q * 4);
            CP_COMMIT();
        }
        if (seg == 0) { sAu[row] = a; sPb[row] = pb; }
    }

    // ---- load + plane-permute K ----
    #pragma unroll
    for (int it = 0; it < 16; it++) {
        int f = tid + it * 512;
        int kk = f >> 6, c4 = f & 63;
        float4 v = reinterpret_cast<const float4*>(K + (size_t)kk * 256)[c4];
        int g     = c4 >> 4;
        int p     = (c4 & 15) * 2;
        int plane = g >> 1;
        int gpos  = (g & 1) * 2;
        float2* d0 = reinterpret_cast<float2*>(&sKp[kk * 256 + plane * 128 + p * 4 + gpos]);
        float2* d1 = reinterpret_cast<float2*>(&sKp[kk * 256 + plane * 128 + (p + 1) * 4 + gpos]);
        *d0 = make_float2(v.x, v.y);
        *d1 = make_float2(v.z, v.w);
    }

    float2 bg[4];
    #pragma unroll
    for (int g = 0; g < 4; g++)
        bg[g] = *reinterpret_cast<const float2*>(bias + g * 64 + hx);

    float2 cc[8];
    #pragma unroll
    for (int i = 0; i < 8; i++) cc[i] = make_float2(0.f, 0.f);

    const unsigned wbase = sKp_a + (unsigned)(tx * 4) * 4u;

    for (int t = 0; t < mx; t++) {
        asm volatile("cp.async.wait_group 1;" ::: "memory");
        __syncthreads();

        const float* xb = xbuf + (t & 1) * 8192;

        u64 acc[8][4];
        #pragma unroll
        for (int i = 0; i < 8; i++)
            #pragma unroll
            for (int g = 0; g < 4; g++) acc[i][g] = 0ull;

        // ---- GEMM, x half ----
        #pragma unroll 2
        for (int k = 0; k < 64; k += 2) {
            u64 wi0, wj0, wf0, wo0, wi1, wj1, wf1, wo1;
            lds_v2u64(wi0, wj0, wbase + (unsigned)(k * 256) * 4u);
            lds_v2u64(wf0, wo0, wbase + (unsigned)(k * 256 + 128) * 4u);
            lds_v2u64(wi1, wj1, wbase + (unsigned)((k + 1) * 256) * 4u);
            lds_v2u64(wf1, wo1, wbase + (unsigned)((k + 1) * 256 + 128) * 4u);
            #pragma unroll
            for (int i = 0; i < 8; i++) {
                float2 a = *reinterpret_cast<const float2*>(&xb[(r0 + i) * 64 + k]);
                u64 sx = splat2(a.x), sy = splat2(a.y);
                ffma2(acc[i][0], sx, wi0); ffma2(acc[i][1], sx, wj0);
                ffma2(acc[i][2], sx, wf0); ffma2(acc[i][3], sx, wo0);
                ffma2(acc[i][0], sy, wi1); ffma2(acc[i][1], sy, wj1);
                ffma2(acc[i][2], sy, wf1); ffma2(acc[i][3], sy, wo1);
            }
        }

        // ---- GEMM, h half (skipped on t == 0) ----
        if (t > 0) {
            #pragma unroll 2
            for (int k = 0; k < 64; k += 2) {
                u64 wi0, wj0, wf0, wo0, wi1, wj1, wf1, wo1;
                lds_v2u64(wi0, wj0, wbase + (unsigned)((k + 64) * 256) * 4u);
                lds_v2u64(wf0, wo0, wbase + (unsigned)((k + 64) * 256 + 128) * 4u);
                lds_v2u64(wi1, wj1, wbase + (unsigned)((k + 65) * 256) * 4u);
                lds_v2u64(wf1, wo1, wbase + (unsigned)((k + 65) * 256 + 128) * 4u);
                #pragma unroll
                for (int i = 0; i < 8; i++) {
                    float2 a = *reinterpret_cast<const float2*>(&sH[(r0 + i) * 66 + k]);
                    u64 sx = splat2(a.x), sy = splat2(a.y);
                    ffma2(acc[i][0], sx, wi0); ffma2(acc[i][1], sx, wj0);
                    ffma2(acc[i][2], sx, wf0); ffma2(acc[i][3], sx, wo0);
                    ffma2(acc[i][0], sy, wi1); ffma2(acc[i][1], sy, wj1);
                    ffma2(acc[i][2], sy, wf1); ffma2(acc[i][3], sy, wo1);
                }
            }
        }

        __syncthreads();

        // ---- prefetch x_{t+2} if that step will run ----
        if (t + 2 < mx) {
            int row = tid >> 2, seg = tid & 3;
            int pb = sPb[row];
            int tt = t + 2;
            int a = sAu[row];
            int ts = dir ? ((tt < a) ? (a - 1 - tt) : tt) : tt;
            const float* src = g_x + ((size_t)pb * 5 + ts) * 64 + seg * 16;
            unsigned dst = (unsigned)__cvta_generic_to_shared(xbuf + (tt & 1) * 8192 + row * 64 + seg * 16);
            #pragma unroll
            for (int q = 0; q < 4; q++) CP16(dst + q * 16, src + q * 4);
            CP_COMMIT();
        }

        // ---- gate epilogue ----
        #pragma unroll
        for (int i = 0; i < 8; i++) {
            int row = r0 + i;
            int a = sAu[row];
            bool valid = (t < a);
            float2 gi = unpack2(acc[i][0]);
            float2 gj = unpack2(acc[i][1]);
            float2 gf = unpack2(acc[i][2]);
            float2 go = unpack2(acc[i][3]);
            gi.x += bg[0].x; gi.y += bg[0].y;
            gj.x += bg[1].x; gj.y += bg[1].y;
            gf.x += bg[2].x; gf.y += bg[2].y;
            go.x += bg[3].x; go.y += bg[3].y;

            float2 hold = (t > 0) ? *reinterpret_cast<const float2*>(&sH[row * 66 + hx])
                                  : make_float2(0.f, 0.f);
            float2 cold = cc[i];

            float cnx = sig_f(gf.x + 1.f) * cold.x + sig_f(gi.x) * tanh_f(gj.x);
            float cny = sig_f(gf.y + 1.f) * cold.y + sig_f(gi.y) * tanh_f(gj.y);
            float hnx = sig_f(go.x) * tanh_f(cnx);
            float hny = sig_f(go.y) * tanh_f(cny);

            cc[i].x = valid ? cnx : cold.x;
            cc[i].y = valid ? cny : cold.y;
            float2 hw = make_float2(valid ? hnx : hold.x, valid ? hny : hold.y);
            *reinterpret_cast<float2*>(&sH[row * 66 + hx]) = hw;

            float2 yw = make_float2(valid ? hnx : 0.f, valid ? hny : 0.f);
            *reinterpret_cast<float2*>(gy + ((size_t)sPb[row] * 5 + t) * 64 + hx) = yw;
        }
    }
    asm volatile("cp.async.wait_group 0;" ::: "memory");
}

// =====================================================================================
// Kernel 3: LN over (T,2H) + relu + conv dot + masked sum. Warp per batch.
// Substitutes exact zeros for t >= au (those ys slots are never written now).
// =====================================================================================
__global__ __launch_bounds__(256)
void final_kernel(const float* __restrict__ mask,
                  const float* __restrict__ ln3g, const float* __restrict__ ln3b,
                  const float* __restrict__ convw, const float* __restrict__ convb,
                  const int* __restrict__ au, float* __restrict__ out)
{
    int b = blockIdx.x * 8 + (threadIdx.x >> 5);
    int lane = threadIdx.x & 31;
    int a = au[b];

    float vals[20];
    float s = 0.f, q = 0.f;
    #pragma unroll
    for (int t = 0; t < 5; t++) {
        float v0 = 0.f, v1 = 0.f, v2 = 0.f, v3 = 0.f;
        if (t < a) {
            int rt = a - 1 - t;
            size_t fbase = ((size_t)b * 5 + t)  * 64;
            size_t bbase = ((size_t)b * 5 + rt) * 64;
            v0 = g_ys[0][fbase + lane];
            v1 = g_ys[0][fbase + lane + 32];
            v2 = g_ys[1][bbase + lane];
            v3 = g_ys[1][bbase + lane + 32];
        }
        vals[t * 4 + 0] = v0; vals[t * 4 + 1] = v1;
        vals[t * 4 + 2] = v2; vals[t * 4 + 3] = v3;
        s += v0 + v1 + v2 + v3;
        q += v0 * v0 + v1 * v1 + v2 * v2 + v3 * v3;
    }
    #pragma unroll
    for (int o = 16; o; o >>= 1) { s += __shfl_xor_sync(~0u, s, o); q += __shfl_xor_sync(~0u, q, o); }
    float m = s * (1.f / 640.f);
    float var = q * (1.f / 640.f) - m * m;
    float rs = rsqrtf(var + EPSf);

    float g0 = ln3g[lane],      c0 = ln3b[lane],      w0 = convw[lane];
    float g1 = ln3g[lane + 32], c1 = ln3b[lane + 32], w1 = convw[lane + 32];
    float g2 = ln3g[lane + 64], c2 = ln3b[lane + 64], w2 = convw[lane + 64];
    float g3 = ln3g[lane + 96], c3 = ln3b[lane + 96], w3 = convw[lane + 96];

    float accq = 0.f, msum = 0.f;
    #pragma unroll
    for (int t = 0; t < 5; t++) {
        float p =
            fmaxf((vals[t*4+0] - m) * rs * g0 + c0, 0.f) * w0 +
            fmaxf((vals[t*4+1] - m) * rs * g1 + c1, 0.f) * w1 +
            fmaxf((vals[t*4+2] - m) * rs * g2 + c2, 0.f) * w2 +
            fmaxf((vals[t*4+3] - m) * rs * g3 + c3, 0.f) * w3;
        float mk = mask[(size_t)b * 5 + t];
        accq += p * mk;
        msum += mk;
    }
    #pragma unroll
    for (int o = 16; o; o >>= 1) accq += __shfl_xor_sync(~0u, accq, o);
    if (lane == 0) out[b] = accq + convb[0] * msum;
}

// =====================================================================================
extern "C" void kernel_launch(void* const* d_in, const int* in_sizes, int n_in,
                              void* d_out, int out_size)
{
    (void)in_sizes; (void)n_in; (void)out_size;
    const float* ud     = (const float*)d_in[0];
    const float* action = (const float*)d_in[1];
    const float* mask   = (const float*)d_in[2];
    const float* ln0g   = (const float*)d_in[3];
    const float* ln0b   = (const float*)d_in[4];
    const float* W1     = (const float*)d_in[5];
    const float* b1     = (const float*)d_in[6];
    const float* ln1g   = (const float*)d_in[7];
    const float* ln1b   = (const float*)d_in[8];
    const float* W2     = (const float*)d_in[9];
    const float* b2     = (const float*)d_in[10];
    const float* ln2g   = (const float*)d_in[11];
    const float* ln2b   = (const float*)d_in[12];
    const float* fw_k   = (const float*)d_in[13];
    const float* fw_b   = (const float*)d_in[14];
    const float* bw_k   = (const float*)d_in[15];
    const float* bw_b   = (const float*)d_in[16];
    const float* ln3g   = (const float*)d_in[17];
    const float* ln3b   = (const float*)d_in[18];
    const float* convw  = (const float*)d_in[19];
    const float* convb  = (const float*)d_in[20];
    const int*   au     = (const int*)d_in[21];

    const int MLP_SMEM  = (128*64 + 64*132 + 64*100 + 640) * 4;   // 94720 B
    const int LSTM_SMEM = (57728 + 256) * 4;                      // 231936 B

    cudaFuncSetAttribute(mlp_kernel,             cudaFuncAttributeMaxDynamicSharedMemorySize, MLP_SMEM);
    cudaFuncSetAttribute(lstm_persistent_kernel, cudaFuncAttributeMaxDynamicSharedMemorySize, LSTM_SMEM);

    // sort rows by au (descending)
    zero_cnt_kernel<<<1, 32>>>();
    hist_kernel<<<Bn / 512, 512>>>(au);
    prefix_kernel<<<1, 32>>>();
    scatter_kernel<<<Bn / 512, 512>>>(au);

    mlp_kernel<<<BT / 64, 256, MLP_SMEM>>>(ud, action, ln0g, ln0b, W1, b1,
                                           ln1g, ln1b, W2, b2, ln2g, ln2b);

    lstm_persistent_kernel<<<dim3(Bn / 128, 2), 512, LSTM_SMEM>>>(fw_k, fw_b, bw_k, bw_b, au);

    final_kernel<<<Bn / 8, 256>>>(mask, ln3g, ln3b, convw, convb, au, (float*)d_out);
}